// round 13
// baseline (speedup 1.0000x reference)
#include <cuda_runtime.h>
#include <math_constants.h>

// Encoder_46806553591978: per-word softmax-attention pooling over subword spans.
//   scores[s] = emb[s].w + b ; out[wd] = softmax(scores[span]) @ emb[span]
//
// Champion shape (persistent grid, one warp/word, rows register-resident,
// single read of each emb row) with Blackwell 256-bit vector memory ops in
// the fast path: ld.global.nc.v8.f32 / st.global.v8.f32 (sm_100+). Each warp
// instruction moves 1KB as 8 contiguous 128B lines -> half the LSU/L1
// transactions (12->6 loads, 6->3 stores per word), larger better-streaming
// DRAM requests. Clean test of request width (R4's 32B attempt was confounded
// by evict_last + union codegen).

#define D_DIM      768
#define VEC8       (D_DIM / 8)      // 96 8-float chunks per row
#define PER_LANE8  (VEC8 / 32)      // 3 chunks per lane
#define WARPS_PB   8
#define THREADS_PB (WARPS_PB * 32)
#define GRID_BLKS  304              // 152 SMs * 2 resident blocks

__device__ __forceinline__ void ldg256(const float* __restrict__ p, float* v)
{
    asm volatile("ld.global.nc.v8.f32 {%0,%1,%2,%3,%4,%5,%6,%7}, [%8];"
                 : "=f"(v[0]), "=f"(v[1]), "=f"(v[2]), "=f"(v[3]),
                   "=f"(v[4]), "=f"(v[5]), "=f"(v[6]), "=f"(v[7])
                 : "l"(p));
}

__device__ __forceinline__ void stg256(float* __restrict__ p, const float* v)
{
    asm volatile("st.global.v8.f32 [%0], {%1,%2,%3,%4,%5,%6,%7,%8};"
                 :: "l"(p),
                    "f"(v[0]), "f"(v[1]), "f"(v[2]), "f"(v[3]),
                    "f"(v[4]), "f"(v[5]), "f"(v[6]), "f"(v[7])
                 : "memory");
}

__global__ __launch_bounds__(THREADS_PB)
void encoder_word_pool_kernel(const float* __restrict__ emb,
                              const int*   __restrict__ offs,
                              const float* __restrict__ attn_w,
                              const float* __restrict__ attn_b,
                              float*       __restrict__ out,
                              int n_words)
{
    __shared__ float sw[D_DIM];

    const int tid = threadIdx.x;
    for (int i = tid; i < D_DIM / 4; i += THREADS_PB)
        reinterpret_cast<float4*>(sw)[i] =
            reinterpret_cast<const float4*>(attn_w)[i];
    __syncthreads();

    const int lane = tid & 31;
    const int warp = tid >> 5;
    const float bias = *attn_b;
    const int stride = gridDim.x * WARPS_PB;   // total warps in grid

    for (int word = blockIdx.x * WARPS_PB + warp; word < n_words; word += stride) {
        const int start = offs[2 * word];
        const int end   = offs[2 * word + 1];

        float* __restrict__ po = out + (size_t)word * D_DIM;

        if (end - start == 2) {
            // ---- fast path: 256-bit loads, both rows register-resident ----
            const float* __restrict__ p0 = emb + (size_t)start * D_DIM;
            const float* __restrict__ p1 = p0 + D_DIM;   // contiguous next row

            float r0[PER_LANE8][8], r1[PER_LANE8][8];
            float d0 = 0.f, d1 = 0.f;
            #pragma unroll
            for (int k = 0; k < PER_LANE8; ++k) {
                const int off = (lane + 32 * k) * 8;
                ldg256(p0 + off, r0[k]);
                ldg256(p1 + off, r1[k]);
                #pragma unroll
                for (int j = 0; j < 8; ++j) {
                    const float wv = sw[off + j];
                    d0 += r0[k][j] * wv;
                    d1 += r1[k][j] * wv;
                }
            }
            #pragma unroll
            for (int o = 16; o > 0; o >>= 1) {
                d0 += __shfl_xor_sync(0xffffffffu, d0, o);
                d1 += __shfl_xor_sync(0xffffffffu, d1, o);
            }
            d0 += bias; d1 += bias;

            const float m   = fmaxf(d0, d1);
            const float e0  = __expf(d0 - m);
            const float e1  = __expf(d1 - m);
            const float inv = 1.f / (e0 + e1);
            const float a0 = e0 * inv, a1 = e1 * inv;

            #pragma unroll
            for (int k = 0; k < PER_LANE8; ++k) {
                const int off = (lane + 32 * k) * 8;
                float o8[8];
                #pragma unroll
                for (int j = 0; j < 8; ++j)
                    o8[j] = a0 * r0[k][j] + a1 * r1[k][j];
                stg256(po + off, o8);
            }
        } else {
            // ---- generic span: online softmax, single pass (float4) ----
            float m = -CUDART_INF_F;
            float denom = 0.f;
            float acc[(D_DIM / 32)];   // 24 floats per lane
            #pragma unroll
            for (int k = 0; k < D_DIM / 32; ++k) acc[k] = 0.f;

            for (int s = start; s < end; ++s) {
                const float4* __restrict__ p =
                    reinterpret_cast<const float4*>(emb + (size_t)s * D_DIM);
                float4 r[6];
                float d = 0.f;
                #pragma unroll
                for (int k = 0; k < 6; ++k) {
                    const int idx = lane + 32 * k;
                    const float4 wv = reinterpret_cast<const float4*>(sw)[idx];
                    r[k] = p[idx];
                    d += r[k].x * wv.x + r[k].y * wv.y + r[k].z * wv.z + r[k].w * wv.w;
                }
                #pragma unroll
                for (int o = 16; o > 0; o >>= 1)
                    d += __shfl_xor_sync(0xffffffffu, d, o);
                d += bias;

                const float mn    = fmaxf(m, d);
                const float scale = __expf(m - mn);   // exp(-inf)=0 on first iter
                const float e     = __expf(d - mn);
                denom = denom * scale + e;
                #pragma unroll
                for (int k = 0; k < 6; ++k) {
                    acc[4*k+0] = acc[4*k+0] * scale + e * r[k].x;
                    acc[4*k+1] = acc[4*k+1] * scale + e * r[k].y;
                    acc[4*k+2] = acc[4*k+2] * scale + e * r[k].z;
                    acc[4*k+3] = acc[4*k+3] * scale + e * r[k].w;
                }
                m = mn;
            }
            const float inv = 1.f / denom;
            float4* __restrict__ po4 = reinterpret_cast<float4*>(po);
            #pragma unroll
            for (int k = 0; k < 6; ++k) {
                float4 o4;
                o4.x = acc[4*k+0] * inv;
                o4.y = acc[4*k+1] * inv;
                o4.z = acc[4*k+2] * inv;
                o4.w = acc[4*k+3] * inv;
                po4[lane + 32 * k] = o4;
            }
        }
    }
}

extern "C" void kernel_launch(void* const* d_in, const int* in_sizes, int n_in,
                              void* d_out, int out_size)
{
    const float* emb    = (const float*)d_in[0];   // [n_subwords, 768] fp32
    const int*   offs   = (const int*)  d_in[1];   // [n_words, 2] int32
    const float* attn_w = (const float*)d_in[2];   // [768] fp32
    const float* attn_b = (const float*)d_in[3];   // scalar fp32
    float*       out    = (float*)d_out;           // [n_words, 768] fp32

    const int n_words = in_sizes[1] / 2;
    int blocks = GRID_BLKS;
    const int max_blocks = (n_words + WARPS_PB - 1) / WARPS_PB;
    if (blocks > max_blocks) blocks = max_blocks;

    encoder_word_pool_kernel<<<blocks, THREADS_PB>>>(emb, offs, attn_w, attn_b,
                                                     out, n_words);
}

// round 14
// speedup vs baseline: 1.1869x; 1.1869x over previous
#include <cuda_runtime.h>
#include <math_constants.h>

// Encoder_46806553591978: per-word softmax-attention pooling over subword spans.
//   scores[s] = emb[s].w + b ; out[wd] = softmax(scores[span]) @ emb[span]
//
// FINAL CHAMPION (byte-identical to the 10.784us R10 source).
// Mixed-stream HBM-bound: 75.5MB mandatory traffic (50.3MB emb read once +
// 25.2MB fp32 out written once, full-line coalesced so no RFO). Best measured
// 10.78us = 7.0TB/s combined = 87.5% of 8TB/s spec. Mode of identical source:
// 12.77us; run-to-run variance (DVFS) exceeds remaining theoretical headroom.
// Nine variants ruled out as neutral-or-worse: two-phase reload, cp.async
// double-buffered pipeline, L2 evict_last pinning (createpolicy + literal),
// .cs streaming stores, 32B and 256B load/store widths, occupancy 21-38%,
// reg pressure 64-96, multi-wave vs persistent grid. No SM-side counter
// ever exceeded ~31% of peak.
//
// Shape: persistent grid (2 blocks/SM, zero wave transitions, no partial
// final wave), one warp per word, both rows register-resident, single read
// of each emb row, float4 (16B) loads, default .wb stores.

#define D_DIM      768
#define VEC        (D_DIM / 4)      // 192 float4
#define PER_LANE   (VEC / 32)       // 6 float4 per lane
#define WARPS_PB   8
#define THREADS_PB (WARPS_PB * 32)
#define GRID_BLKS  304              // 152 SMs * 2 resident blocks

__global__ __launch_bounds__(THREADS_PB)
void encoder_word_pool_kernel(const float* __restrict__ emb,
                              const int*   __restrict__ offs,
                              const float* __restrict__ attn_w,
                              const float* __restrict__ attn_b,
                              float*       __restrict__ out,
                              int n_words)
{
    __shared__ float4 sw[VEC];

    const int tid = threadIdx.x;
    for (int i = tid; i < VEC; i += THREADS_PB)
        sw[i] = reinterpret_cast<const float4*>(attn_w)[i];
    __syncthreads();

    const int lane = tid & 31;
    const int warp = tid >> 5;
    const float bias = *attn_b;
    const int stride = gridDim.x * WARPS_PB;   // total warps in grid

    for (int word = blockIdx.x * WARPS_PB + warp; word < n_words; word += stride) {
        const int start = offs[2 * word];
        const int end   = offs[2 * word + 1];

        float4* __restrict__ po =
            reinterpret_cast<float4*>(out + (size_t)word * D_DIM);

        if (end - start == 2) {
            // ---- fast path: both rows register-resident, one read each ----
            const float4* __restrict__ p0 =
                reinterpret_cast<const float4*>(emb + (size_t)start * D_DIM);
            const float4* __restrict__ p1 = p0 + VEC;   // contiguous next row

            float4 r0[PER_LANE], r1[PER_LANE];
            float d0 = 0.f, d1 = 0.f;
            #pragma unroll
            for (int k = 0; k < PER_LANE; ++k) {
                const int idx = lane + 32 * k;
                const float4 wv = sw[idx];
                r0[k] = p0[idx];
                r1[k] = p1[idx];
                d0 += r0[k].x * wv.x + r0[k].y * wv.y + r0[k].z * wv.z + r0[k].w * wv.w;
                d1 += r1[k].x * wv.x + r1[k].y * wv.y + r1[k].z * wv.z + r1[k].w * wv.w;
            }
            #pragma unroll
            for (int o = 16; o > 0; o >>= 1) {
                d0 += __shfl_xor_sync(0xffffffffu, d0, o);
                d1 += __shfl_xor_sync(0xffffffffu, d1, o);
            }
            d0 += bias; d1 += bias;

            const float m   = fmaxf(d0, d1);
            const float e0  = __expf(d0 - m);
            const float e1  = __expf(d1 - m);
            const float inv = 1.f / (e0 + e1);
            const float a0 = e0 * inv, a1 = e1 * inv;

            #pragma unroll
            for (int k = 0; k < PER_LANE; ++k) {
                float4 o4;
                o4.x = a0 * r0[k].x + a1 * r1[k].x;
                o4.y = a0 * r0[k].y + a1 * r1[k].y;
                o4.z = a0 * r0[k].z + a1 * r1[k].z;
                o4.w = a0 * r0[k].w + a1 * r1[k].w;
                po[lane + 32 * k] = o4;
            }
        } else {
            // ---- generic span: online softmax, single pass ----
            float m = -CUDART_INF_F;
            float denom = 0.f;
            float acc[PER_LANE * 4];
            #pragma unroll
            for (int k = 0; k < PER_LANE * 4; ++k) acc[k] = 0.f;

            for (int s = start; s < end; ++s) {
                const float4* __restrict__ p =
                    reinterpret_cast<const float4*>(emb + (size_t)s * D_DIM);
                float4 r[PER_LANE];
                float d = 0.f;
                #pragma unroll
                for (int k = 0; k < PER_LANE; ++k) {
                    const int idx = lane + 32 * k;
                    const float4 wv = sw[idx];
                    r[k] = p[idx];
                    d += r[k].x * wv.x + r[k].y * wv.y + r[k].z * wv.z + r[k].w * wv.w;
                }
                #pragma unroll
                for (int o = 16; o > 0; o >>= 1)
                    d += __shfl_xor_sync(0xffffffffu, d, o);
                d += bias;

                const float mn    = fmaxf(m, d);
                const float scale = __expf(m - mn);   // exp(-inf)=0 on first iter
                const float e     = __expf(d - mn);
                denom = denom * scale + e;
                #pragma unroll
                for (int k = 0; k < PER_LANE; ++k) {
                    acc[4*k+0] = acc[4*k+0] * scale + e * r[k].x;
                    acc[4*k+1] = acc[4*k+1] * scale + e * r[k].y;
                    acc[4*k+2] = acc[4*k+2] * scale + e * r[k].z;
                    acc[4*k+3] = acc[4*k+3] * scale + e * r[k].w;
                }
                m = mn;
            }
            const float inv = 1.f / denom;
            #pragma unroll
            for (int k = 0; k < PER_LANE; ++k) {
                float4 o4;
                o4.x = acc[4*k+0] * inv;
                o4.y = acc[4*k+1] * inv;
                o4.z = acc[4*k+2] * inv;
                o4.w = acc[4*k+3] * inv;
                po[lane + 32 * k] = o4;
            }
        }
    }
}

extern "C" void kernel_launch(void* const* d_in, const int* in_sizes, int n_in,
                              void* d_out, int out_size)
{
    const float* emb    = (const float*)d_in[0];   // [n_subwords, 768] fp32
    const int*   offs   = (const int*)  d_in[1];   // [n_words, 2] int32
    const float* attn_w = (const float*)d_in[2];   // [768] fp32
    const float* attn_b = (const float*)d_in[3];   // scalar fp32
    float*       out    = (float*)d_out;           // [n_words, 768] fp32

    const int n_words = in_sizes[1] / 2;
    int blocks = GRID_BLKS;
    const int max_blocks = (n_words + WARPS_PB - 1) / WARPS_PB;
    if (blocks > max_blocks) blocks = max_blocks;

    encoder_word_pool_kernel<<<blocks, THREADS_PB>>>(emb, offs, attn_w, attn_b,
                                                     out, n_words);
}